// round 13
// baseline (speedup 1.0000x reference)
#include <cuda_runtime.h>
#include <cuda_fp16.h>
#include <stdint.h>

// ============================================================================
// CrossAttention collapses algebraically:
//   softmax over k sums to 1 per query -> sum over (q,k) of scores = L = 2048.
//   einsum 'bvhd,bhqk->bvhd' has no shared contraction index, so attn = v*2048:
//     out = 2048 * x @ (Wv@Wo) + (2048 * bv@Wo + bo)
// encoder_x / Wq / bq / Wk / bk are dead inputs.
//
// R13: gemm2's fp32-A fragment path (64B/lane LDS.64 + 16-CVT chains) was the
// gap to its ~30us floor. x is now pre-converted to fp16 by 512 extra CTAs
// folded into gemm1's launch (y>=17), and gemm2 uses ldmatrix for BOTH
// operands (R5's proven fp16-A fragment map) on R8's winning geometry.
// ============================================================================

// ---------------- scratch ----------------------------------------------------
__device__ __half g_xh  [8192u * 1024u];
__device__ __half g_WcTh[1024u * 1024u];
__device__ float  g_t[1024];

// ---------------- helpers ----------------------------------------------------
__device__ __forceinline__ uint32_t smem_u32(const void* p) {
    uint32_t a;
    asm("{ .reg .u64 t; cvta.to.shared.u64 t, %1; cvt.u32.u64 %0, t; }"
        : "=r"(a) : "l"(p));
    return a;
}
__device__ __forceinline__ void cp_async16(uint32_t saddr, const void* gaddr) {
    asm volatile("cp.async.cg.shared.global [%0], [%1], 16;"
                 :: "r"(saddr), "l"(gaddr));
}
#define CP_COMMIT() asm volatile("cp.async.commit_group;" ::: "memory")
#define CP_WAIT0()  asm volatile("cp.async.wait_group 0;" ::: "memory")

__device__ __forceinline__ void mma16816(float* c, const uint32_t* a,
                                         const uint32_t* b) {
    asm volatile(
        "mma.sync.aligned.m16n8k16.row.col.f32.f16.f16.f32 "
        "{%0,%1,%2,%3}, {%4,%5,%6,%7}, {%8,%9}, {%0,%1,%2,%3};"
        : "+f"(c[0]), "+f"(c[1]), "+f"(c[2]), "+f"(c[3])
        : "r"(a[0]), "r"(a[1]), "r"(a[2]), "r"(a[3]), "r"(b[0]), "r"(b[1]));
}
__device__ __forceinline__ void ldsm4(uint32_t* r, uint32_t addr) {
    asm volatile("ldmatrix.sync.aligned.m8n8.x4.shared.b16 {%0,%1,%2,%3}, [%4];"
                 : "=r"(r[0]), "=r"(r[1]), "=r"(r[2]), "=r"(r[3]) : "r"(addr));
}
// fp16 tile (128B rows): 16B-granule XOR swizzle
__device__ __forceinline__ uint32_t swzH(int row, int col) {
    return (uint32_t)(row * 128 + (col ^ ((row & 7) << 4)));
}
// fp32 tile (256B rows): 32B-granule XOR swizzle
__device__ __forceinline__ uint32_t swzF(int row, int col) {
    return (uint32_t)(row * 256 + (col ^ ((row & 7) << 5)));
}
__device__ __forceinline__ uint32_t h2u(__half2 h) {
    union { __half2 h; uint32_t u; } c; c.h = h; return c.u;
}
__device__ __forceinline__ uint32_t f2h2(float a, float b) {
    return h2u(__floats2half2_rn(a, b));
}

// ============================================================================
// gemm1 launch:  y<16: WcT[m,n] = sum_k Wo[k,m]*Wv[n,k]  (64x64 tiles)
//                y==16: bias t[j] = 2048*sum_i bv[i]*Wo[i,j] + bo[j]
//                y>=17: x fp32 -> fp16 conversion (512 CTAs)
// ============================================================================
#define G1T 128
constexpr uint32_t G1_AT  = 64u * 272u;
constexpr uint32_t G1_BT  = 64u * 256u;
constexpr uint32_t G1_STG = G1_AT + G1_BT;
constexpr uint32_t SM_G1  = 2u * G1_STG;

__global__ __launch_bounds__(G1T)
void gemm1_w(const float* __restrict__ Wo, const float* __restrict__ Wv,
             const float* __restrict__ x, __half* __restrict__ xh,
             __half* __restrict__ WcT,
             const float* __restrict__ bv, const float* __restrict__ bo,
             float* __restrict__ tvec)
{
    const int tid = threadIdx.x;

    if (blockIdx.y >= 17) {     // ---- x conversion CTAs (512)
        const int cta = (blockIdx.y - 17) * 16 + blockIdx.x;   // 0..511
        const int base = cta * 4096;                            // float4 units
        #pragma unroll 8
        for (int i = 0; i < 32; i++) {
            const int idx = base + i * G1T + tid;
            const float4 v = ((const float4*)x)[idx];
            ((__half2*)xh)[2 * idx]     = __floats2half2_rn(v.x, v.y);
            ((__half2*)xh)[2 * idx + 1] = __floats2half2_rn(v.z, v.w);
        }
        return;
    }

    if (blockIdx.y == 16) {     // ---- bias CTAs (16)
        __shared__ float red[2][64];
        const int c = tid & 63, q = tid >> 6;
        const int j = blockIdx.x * 64 + c;
        const int i0 = q * 512;
        float s = 0.0f;
        #pragma unroll 16
        for (int i = 0; i < 512; i++)
            s = fmaf(bv[i0 + i], Wo[(size_t)(i0 + i) * 1024 + j], s);
        red[q][c] = s;
        __syncthreads();
        if (q == 0)
            tvec[j] = 2048.0f * (red[0][c] + red[1][c]) + bo[j];
        return;
    }

    // ---- GEMM CTAs (256) ---------------------------------------------------
    extern __shared__ char smem[];
    const uint32_t sb = smem_u32(smem);
    const int wid = tid >> 5, lane = tid & 31;
    const int g = lane >> 2, tig = lane & 3;
    const int mb = blockIdx.y * 64;
    const int nb = blockIdx.x * 64;
    const int wm = (wid & 1) * 32;
    const int wn = (wid >> 1) * 32;

    float acc[2][4][4];
    #pragma unroll
    for (int mt = 0; mt < 2; mt++)
        #pragma unroll
        for (int nt = 0; nt < 4; nt++)
            #pragma unroll
            for (int i = 0; i < 4; i++) acc[mt][nt][i] = 0.0f;

    auto issue = [&](int c) {
        const int k0 = c * 64;
        const uint32_t stg = sb + (uint32_t)(c & 1) * G1_STG;
        #pragma unroll
        for (int i = 0; i < 8; i++) {          // A: Wo rows, 272B pitch
            const int li = i * G1T + tid;
            const int r = li >> 4, gc = li & 15;
            cp_async16(stg + (uint32_t)(r * 272 + gc * 16),
                       Wo + (size_t)(k0 + r) * 1024 + mb + gc * 4);
        }
        #pragma unroll
        for (int i = 0; i < 8; i++) {          // B: Wv rows, swzF
            const int li = i * G1T + tid;
            const int r = li >> 4, gc = li & 15;
            cp_async16(stg + G1_AT + swzF(r, gc * 16),
                       Wv + (size_t)(nb + r) * 1024 + k0 + gc * 4);
        }
        CP_COMMIT();
    };

    issue(0);

    for (int c = 0; c < 16; c++) {
        CP_WAIT0();
        __syncthreads();
        if (c + 1 < 16) issue(c + 1);

        const char* baseA = smem + (size_t)(c & 1) * G1_STG;
        const char* baseB = baseA + G1_AT;

        #pragma unroll
        for (int ks = 0; ks < 4; ks++) {
            const int ka = ks * 16 + tig * 2;
            uint32_t aF[2][4], bF[4][2];

            #pragma unroll
            for (int mt = 0; mt < 2; mt++) {
                const int m0 = wm + mt * 16 + g, m1 = m0 + 8;
                const char* r0p = baseA + ka * 272;
                const char* r1p = r0p + 272;
                const char* r8p = r0p + 8 * 272;
                const char* r9p = r8p + 272;
                aF[mt][0] = f2h2(*(const float*)(r0p + m0 * 4),
                                 *(const float*)(r1p + m0 * 4));
                aF[mt][1] = f2h2(*(const float*)(r0p + m1 * 4),
                                 *(const float*)(r1p + m1 * 4));
                aF[mt][2] = f2h2(*(const float*)(r8p + m0 * 4),
                                 *(const float*)(r9p + m0 * 4));
                aF[mt][3] = f2h2(*(const float*)(r8p + m1 * 4),
                                 *(const float*)(r9p + m1 * 4));
            }
            #pragma unroll
            for (int nt = 0; nt < 4; nt++) {
                const int row = wn + nt * 8 + g;
                const int cb = ka * 4;
                float2 lo = *(const float2*)(baseB + swzF(row, cb));
                float2 hi = *(const float2*)(baseB + swzF(row, cb + 32));
                bF[nt][0] = f2h2(lo.x, lo.y);
                bF[nt][1] = f2h2(hi.x, hi.y);
            }
            #pragma unroll
            for (int mt = 0; mt < 2; mt++)
                #pragma unroll
                for (int nt = 0; nt < 4; nt++)
                    mma16816(acc[mt][nt], aF[mt], bF[nt]);
        }
        __syncthreads();
    }

    #pragma unroll
    for (int mt = 0; mt < 2; mt++) {
        const size_t r0 = (size_t)mb + wm + mt * 16 + g;
        #pragma unroll
        for (int nt = 0; nt < 4; nt++) {
            const int c0 = nb + wn + nt * 8 + tig * 2;
            *(__half2*)(WcT + r0 * 1024 + c0) =
                __floats2half2_rn(acc[mt][nt][0], acc[mt][nt][1]);
            *(__half2*)(WcT + (r0 + 8) * 1024 + c0) =
                __floats2half2_rn(acc[mt][nt][2], acc[mt][nt][3]);
        }
    }
}

// ============================================================================
// gemm2: out[m,n] = 2048 * sum_k xh[m,k] * WcT[n,k] + t[n]
// R8 geometry, all-fp16 operands: BM=64, BN=128, 4 warps, warp tile 32x64.
// A and B fragments both via ldmatrix (swzH). 1024 CTAs, 3 CTAs/SM.
// ============================================================================
#define G2T 128
constexpr uint32_t G2_AT  = 64u * 128u;          // 8192  (fp16 A)
constexpr uint32_t G2_BT  = 128u * 128u;         // 16384 (fp16 B)
constexpr uint32_t G2_STG = G2_AT + G2_BT;       // 24576
constexpr uint32_t SM_G2  = 2u * G2_STG;         // 49152

__global__ __launch_bounds__(G2T, 3)
void gemm2_x(const __half* __restrict__ A, const __half* __restrict__ B,
             float* __restrict__ C, const float* __restrict__ bias)
{
    extern __shared__ char smem[];
    const uint32_t sb = smem_u32(smem);
    const int tid = threadIdx.x;
    const int wid = tid >> 5, lane = tid & 31;
    const int g = lane >> 2, tig = lane & 3;
    const int bm = blockIdx.y, bn = blockIdx.x;
    const int wm = (wid & 1) * 32;
    const int wn = (wid >> 1) * 64;
    const int lm = lane >> 3, lr = lane & 7;
    const int N = 1024, K = 1024;

    const __half* Ab = A + (size_t)bm * 64 * K;
    const __half* Bb = B + (size_t)bn * 128 * K;

    float acc[2][8][4];
    #pragma unroll
    for (int mt = 0; mt < 2; mt++)
        #pragma unroll
        for (int nt = 0; nt < 8; nt++)
            #pragma unroll
            for (int i = 0; i < 4; i++) acc[mt][nt][i] = 0.0f;

    auto issue = [&](int c) {
        const int k0 = c * 64;
        const uint32_t stg = sb + (uint32_t)(c & 1) * G2_STG;
        #pragma unroll
        for (int i = 0; i < 4; i++) {          // A: 64 rows x 8 granules
            const int li = i * G2T + tid;
            const int r = li >> 3, gc = li & 7;
            cp_async16(stg + swzH(r, gc * 16),
                       Ab + (size_t)r * K + k0 + gc * 8);
        }
        #pragma unroll
        for (int i = 0; i < 8; i++) {          // B: 128 rows x 8 granules
            const int li = i * G2T + tid;
            const int r = li >> 3, gc = li & 7;
            cp_async16(stg + G2_AT + swzH(r, gc * 16),
                       Bb + (size_t)r * K + k0 + gc * 8);
        }
        CP_COMMIT();
    };

    issue(0);

    for (int c = 0; c < 16; c++) {
        CP_WAIT0();
        __syncthreads();
        if (c + 1 < 16) issue(c + 1);

        const uint32_t tA = sb + (uint32_t)(c & 1) * G2_STG;
        const uint32_t tB = tA + G2_AT;

        #pragma unroll
        for (int ks = 0; ks < 4; ks++) {
            const int kb = ks * 32;
            uint32_t aF[2][4], bF[4][4];

            #pragma unroll
            for (int mt = 0; mt < 2; mt++) {
                const int row = wm + mt * 16 + (lm & 1) * 8 + lr;
                ldsm4(aF[mt], tA + swzH(row, kb + (lm >> 1) * 16));
            }
            #pragma unroll
            for (int nt2 = 0; nt2 < 4; nt2++) {
                const int row = wn + (2 * nt2 + (lm >> 1)) * 8 + lr;
                ldsm4(bF[nt2], tB + swzH(row, kb + (lm & 1) * 16));
            }
            #pragma unroll
            for (int mt = 0; mt < 2; mt++)
                #pragma unroll
                for (int nt2 = 0; nt2 < 4; nt2++) {
                    mma16816(acc[mt][2 * nt2],     aF[mt], &bF[nt2][0]);
                    mma16816(acc[mt][2 * nt2 + 1], aF[mt], &bF[nt2][2]);
                }
        }
        __syncthreads();
    }

    // ---- epilogue
    #pragma unroll
    for (int mt = 0; mt < 2; mt++) {
        const size_t r0 = (size_t)bm * 64 + wm + mt * 16 + g;
        #pragma unroll
        for (int nt = 0; nt < 8; nt++) {
            const int c0 = bn * 128 + wn + nt * 8 + tig * 2;
            const float bx = bias[c0], by = bias[c0 + 1];
            *(float2*)(C + r0 * N + c0) =
                make_float2(2048.0f * acc[mt][nt][0] + bx,
                            2048.0f * acc[mt][nt][1] + by);
            *(float2*)(C + (r0 + 8) * N + c0) =
                make_float2(2048.0f * acc[mt][nt][2] + bx,
                            2048.0f * acc[mt][nt][3] + by);
        }
    }
}

// ---------------------------------------------------------------------------
extern "C" void kernel_launch(void* const* d_in, const int* in_sizes, int n_in,
                              void* d_out, int out_size)
{
    const float* x  = (const float*)d_in[0];
    // d_in[1..5] = encoder_x, Wq, bq, Wk, bk -- mathematically dead
    const float* Wv = (const float*)d_in[6];
    const float* bv = (const float*)d_in[7];
    const float* Wo = (const float*)d_in[8];
    const float* bo = (const float*)d_in[9];
    float* out = (float*)d_out;

    __half *xh, *WcTh;
    float* t;
    cudaGetSymbolAddress((void**)&xh,   g_xh);
    cudaGetSymbolAddress((void**)&WcTh, g_WcTh);
    cudaGetSymbolAddress((void**)&t,    g_t);

    static int smem_set = 0;
    if (!smem_set) {
        cudaFuncSetAttribute(gemm1_w,
                             cudaFuncAttributeMaxDynamicSharedMemorySize, SM_G1);
        cudaFuncSetAttribute(gemm2_x,
                             cudaFuncAttributeMaxDynamicSharedMemorySize, SM_G2);
        smem_set = 1;
    }

    // 1) gemm1 launch: 256 GEMM CTAs + 16 bias CTAs + 512 x-cvt CTAs
    {
        dim3 g(16, 49);   // y<16 gemm, y==16 bias, y>=17 x-cvt
        gemm1_w<<<g, G1T, SM_G1>>>(Wo, Wv, x, xh, WcTh, bv, bo, t);
    }

    // 2) gemm2: out = 2048 * xh @ Wc + t  (1024 CTAs, 4 warps, 3 CTAs/SM)
    {
        dim3 g(8, 128);
        gemm2_x<<<g, G2T, SM_G2>>>(xh, WcTh, out, t);
    }
}